// round 1
// baseline (speedup 1.0000x reference)
#include <cuda_runtime.h>
#include <math.h>

// Problem constants
#define BATCH 2
#define SEQ   2048
#define DIM   1024
#define HEADS 16
#define HDIM  64
#define MROWS (BATCH * SEQ)   // 4096

// Scratch (device globals: allocation-free)
__device__ float g_Q[MROWS * DIM];
__device__ float g_K[MROWS * DIM];
__device__ float g_V[MROWS * DIM];
__device__ float g_A[MROWS * DIM];

// ---------------------------------------------------------------------------
// SGEMM: C[M,N] = A[M,K] * B[N,K]^T + bias[N]
// BM=BN=128, BK=16, 256 threads, 8x8 per-thread micro-tile.
// ---------------------------------------------------------------------------
__global__ __launch_bounds__(256) void sgemm_nt_bias(
    const float* __restrict__ A, const float* __restrict__ Bm,
    const float* __restrict__ bias, float* __restrict__ C,
    int M, int N, int K)
{
    const int BM = 128, BN = 128, BK = 16;
    __shared__ float As[BK][BM];
    __shared__ float Bs[BK][BN];

    const int bx = blockIdx.x;   // N tile
    const int by = blockIdx.y;   // M tile
    const int tid = threadIdx.x;
    const int tr = tid >> 4;     // 0..15 (warp covers 2 tr x 16 tc)
    const int tc = tid & 15;     // 0..15

    float acc[8][8];
#pragma unroll
    for (int i = 0; i < 8; i++)
#pragma unroll
        for (int j = 0; j < 8; j++) acc[i][j] = 0.0f;

    const float* Abase = A + (size_t)(by * BM) * K;
    const float* Bbase = Bm + (size_t)(bx * BN) * K;

    for (int kt = 0; kt < K; kt += BK) {
        // Load tiles: 128x16 floats each = 512 float4, 256 threads -> 2 each
#pragma unroll
        for (int f = tid; f < 512; f += 256) {
            int r  = f >> 2;
            int c4 = (f & 3) << 2;
            float4 va = *(const float4*)(Abase + (size_t)r * K + kt + c4);
            As[c4 + 0][r] = va.x; As[c4 + 1][r] = va.y;
            As[c4 + 2][r] = va.z; As[c4 + 3][r] = va.w;
            float4 vb = *(const float4*)(Bbase + (size_t)r * K + kt + c4);
            Bs[c4 + 0][r] = vb.x; Bs[c4 + 1][r] = vb.y;
            Bs[c4 + 2][r] = vb.z; Bs[c4 + 3][r] = vb.w;
        }
        __syncthreads();

#pragma unroll
        for (int k = 0; k < BK; k++) {
            float ar[8], br[8];
#pragma unroll
            for (int i = 0; i < 8; i += 4) {
                float4 v = *(const float4*)&As[k][tr * 8 + i];
                ar[i] = v.x; ar[i + 1] = v.y; ar[i + 2] = v.z; ar[i + 3] = v.w;
            }
#pragma unroll
            for (int j = 0; j < 8; j += 4) {
                float4 v = *(const float4*)&Bs[k][tc * 8 + j];
                br[j] = v.x; br[j + 1] = v.y; br[j + 2] = v.z; br[j + 3] = v.w;
            }
#pragma unroll
            for (int i = 0; i < 8; i++)
#pragma unroll
                for (int j = 0; j < 8; j++)
                    acc[i][j] += ar[i] * br[j];
        }
        __syncthreads();
    }

    // Epilogue: add bias, store
#pragma unroll
    for (int i = 0; i < 8; i++) {
        int row = by * BM + tr * 8 + i;
        float* crow = C + (size_t)row * N + bx * BN + tc * 8;
        const float* bcol = bias + bx * BN + tc * 8;
#pragma unroll
        for (int j = 0; j < 8; j += 4) {
            float4 o;
            o.x = acc[i][j + 0] + bcol[j + 0];
            o.y = acc[i][j + 1] + bcol[j + 1];
            o.z = acc[i][j + 2] + bcol[j + 2];
            o.w = acc[i][j + 3] + bcol[j + 3];
            *(float4*)(crow + j) = o;
        }
    }
}

// ---------------------------------------------------------------------------
// Flash attention, fp32. grid = (SEQ/64, BATCH*HEADS), 128 threads.
// Thread pair (2t, 2t+1) owns query row r = t; each holds half of the 64-dim
// q vector in registers and half of the 64 output cols. Score partials are
// combined with shfl_xor(.,1). Online softmax; scale x8 folded into q load.
// ---------------------------------------------------------------------------
__global__ __launch_bounds__(128) void flash_attn_f32(
    const float* __restrict__ Q, const float* __restrict__ Kt,
    const float* __restrict__ Vt, float* __restrict__ O)
{
    const int bh = blockIdx.y;
    const int b = bh / HEADS, h = bh % HEADS;
    const int q0 = blockIdx.x * 64;
    const int tid = threadIdx.x;
    const int r = tid >> 1;       // 0..63 query row within tile
    const int half = tid & 1;     // which half of k/out dims

    __shared__ float Ks[32][64];
    __shared__ float Vs[32][64];

    const size_t bhOff = (size_t)b * SEQ * DIM + (size_t)h * HDIM;
    const float* Qb = Q + bhOff;
    const float* Kb = Kt + bhOff;
    const float* Vb = Vt + bhOff;

    // Load my half of q, pre-scaled by 8 (reference divides by hd**-0.5)
    float q[32];
    {
        const float* qp = Qb + (size_t)(q0 + r) * DIM + half * 32;
#pragma unroll
        for (int i = 0; i < 32; i += 4) {
            float4 v = *(const float4*)(qp + i);
            q[i + 0] = v.x * 8.0f; q[i + 1] = v.y * 8.0f;
            q[i + 2] = v.z * 8.0f; q[i + 3] = v.w * 8.0f;
        }
    }

    float m = -INFINITY, l = 0.0f;
    float acc[32];
#pragma unroll
    for (int c = 0; c < 32; c++) acc[c] = 0.0f;

    for (int t0 = 0; t0 < SEQ; t0 += 32) {
        __syncthreads();
        // Load K/V tile: 32 rows x 64 cols = 512 float4 each; 128 thr -> 4 each
#pragma unroll
        for (int f = tid; f < 512; f += 128) {
            int rr = f >> 4;
            int cc = (f & 15) << 2;
            *(float4*)&Ks[rr][cc] =
                *(const float4*)(Kb + (size_t)(t0 + rr) * DIM + cc);
            *(float4*)&Vs[rr][cc] =
                *(const float4*)(Vb + (size_t)(t0 + rr) * DIM + cc);
        }
        __syncthreads();

        // Partial scores over my half of k
        float s[32];
#pragma unroll
        for (int j = 0; j < 32; j++) s[j] = 0.0f;
        for (int kk = 0; kk < 32; kk++) {
            float qv = q[kk];
            int kcol = half * 32 + kk;
#pragma unroll
            for (int j = 0; j < 32; j++)
                s[j] += qv * Ks[j][kcol];
        }
        // Combine halves -> full scores (identical in both pair threads)
#pragma unroll
        for (int j = 0; j < 32; j++)
            s[j] += __shfl_xor_sync(0xffffffffu, s[j], 1);

        // Online softmax update
        float mt = s[0];
#pragma unroll
        for (int j = 1; j < 32; j++) mt = fmaxf(mt, s[j]);
        float mnew = fmaxf(m, mt);
        float corr = __expf(m - mnew);
        float lsum = 0.0f;
#pragma unroll
        for (int j = 0; j < 32; j++) {
            s[j] = __expf(s[j] - mnew);
            lsum += s[j];
        }
        l = l * corr + lsum;
        m = mnew;
#pragma unroll
        for (int c = 0; c < 32; c++) acc[c] *= corr;

        // acc += P * V (my half of output cols)
        for (int j = 0; j < 32; j++) {
            float p = s[j];
            const float* vrow = &Vs[j][half * 32];
#pragma unroll
            for (int c = 0; c < 32; c += 4) {
                float4 v = *(const float4*)(vrow + c);
                acc[c + 0] += p * v.x; acc[c + 1] += p * v.y;
                acc[c + 2] += p * v.z; acc[c + 3] += p * v.w;
            }
        }
    }

    float inv = 1.0f / l;
    float* op = O + bhOff + (size_t)(q0 + r) * DIM + half * 32;
#pragma unroll
    for (int c = 0; c < 32; c += 4) {
        float4 o;
        o.x = acc[c + 0] * inv; o.y = acc[c + 1] * inv;
        o.z = acc[c + 2] * inv; o.w = acc[c + 3] * inv;
        *(float4*)(op + c) = o;
    }
}

// ---------------------------------------------------------------------------
extern "C" void kernel_launch(void* const* d_in, const int* in_sizes, int n_in,
                              void* d_out, int out_size)
{
    (void)in_sizes; (void)n_in; (void)out_size;
    const float* query = (const float*)d_in[0];
    const float* key   = (const float*)d_in[1];
    const float* value = (const float*)d_in[2];
    const float* Wq = (const float*)d_in[3];
    const float* bq = (const float*)d_in[4];
    const float* Wk = (const float*)d_in[5];
    const float* bk = (const float*)d_in[6];
    const float* Wv = (const float*)d_in[7];
    const float* bv = (const float*)d_in[8];
    const float* Wo = (const float*)d_in[9];
    const float* bo = (const float*)d_in[10];
    float* out = (float*)d_out;

    float *qbuf, *kbuf, *vbuf, *abuf;
    cudaGetSymbolAddress((void**)&qbuf, g_Q);
    cudaGetSymbolAddress((void**)&kbuf, g_K);
    cudaGetSymbolAddress((void**)&vbuf, g_V);
    cudaGetSymbolAddress((void**)&abuf, g_A);

    dim3 gemmGrid(DIM / 128, MROWS / 128);   // (8, 32)
    sgemm_nt_bias<<<gemmGrid, 256>>>(query, Wq, bq, qbuf, MROWS, DIM, DIM);
    sgemm_nt_bias<<<gemmGrid, 256>>>(key,   Wk, bk, kbuf, MROWS, DIM, DIM);
    sgemm_nt_bias<<<gemmGrid, 256>>>(value, Wv, bv, vbuf, MROWS, DIM, DIM);

    dim3 attnGrid(SEQ / 64, BATCH * HEADS);  // (32, 32)
    flash_attn_f32<<<attnGrid, 128>>>(qbuf, kbuf, vbuf, abuf);

    sgemm_nt_bias<<<gemmGrid, 256>>>(abuf, Wo, bo, out, MROWS, DIM, DIM);
}

// round 5
// speedup vs baseline: 1.0809x; 1.0809x over previous
#include <cuda_runtime.h>
#include <cuda_bf16.h>
#include <math.h>
#include <stdint.h>

// Problem constants
#define BATCH 2
#define SEQ   2048
#define DIM   1024
#define HEADS 16
#define HDIM  64
#define MROWS (BATCH * SEQ)   // 4096

// Scratch (device globals: allocation-free)
__device__ float g_Q[MROWS * DIM];
__device__ float g_K[MROWS * DIM];
__device__ float g_V[MROWS * DIM];
__device__ float g_A[MROWS * DIM];

// ===========================================================================
// Helpers
// ===========================================================================
__device__ __forceinline__ uint32_t smem_u32(const void* p) {
    uint32_t a;
    asm("{ .reg .u64 t; cvta.to.shared.u64 t, %1; cvt.u32.u64 %0, t; }"
        : "=r"(a) : "l"(p));
    return a;
}

__device__ __forceinline__ void cp16(uint32_t dst, const void* src) {
    asm volatile("cp.async.cg.shared.global [%0], [%1], 16;"
                 :: "r"(dst), "l"(src));
}
#define CP_COMMIT() asm volatile("cp.async.commit_group;" ::: "memory")
#define CP_WAIT1()  asm volatile("cp.async.wait_group 1;" ::: "memory")

// Split float pair into bf16 hi / lo packed registers (lo 16 bits = first elem)
__device__ __forceinline__ void split2(float x0, float x1,
                                       uint32_t& hi, uint32_t& lo) {
    __nv_bfloat16 h0 = __float2bfloat16_rn(x0);
    __nv_bfloat16 h1 = __float2bfloat16_rn(x1);
    float r0 = x0 - __bfloat162float(h0);
    float r1 = x1 - __bfloat162float(h1);
    __nv_bfloat162 hh = __halves2bfloat162(h0, h1);
    __nv_bfloat162 ll = __halves2bfloat162(__float2bfloat16_rn(r0),
                                           __float2bfloat16_rn(r1));
    hi = *reinterpret_cast<uint32_t*>(&hh);
    lo = *reinterpret_cast<uint32_t*>(&ll);
}

__device__ __forceinline__ void mma_bf16(float* c, uint32_t a0, uint32_t a1,
                                         uint32_t a2, uint32_t a3,
                                         uint32_t b0, uint32_t b1) {
    asm volatile(
        "mma.sync.aligned.m16n8k16.row.col.f32.bf16.bf16.f32 "
        "{%0,%1,%2,%3}, {%4,%5,%6,%7}, {%8,%9}, {%0,%1,%2,%3};"
        : "+f"(c[0]), "+f"(c[1]), "+f"(c[2]), "+f"(c[3])
        : "r"(a0), "r"(a1), "r"(a2), "r"(a3), "r"(b0), "r"(b1));
}

// ===========================================================================
// GEMM: C[M,N] = A[M,K] * B[N,K]^T + bias[N], via mma.sync bf16 3x-compensated
// CTA tile 128x128, BK=16, 256 threads (8 warps, 64x32 warp tiles).
// ===========================================================================
#define BMT 128
#define BNT 128
#define BKT 16
#define SSTR 20   // floats per smem row (80B: 16B-aligned, conflict-free)

__global__ __launch_bounds__(256, 1) void gemm_mma_bf16x3(
    const float* __restrict__ A, const float* __restrict__ Bm,
    const float* __restrict__ bias, float* __restrict__ C,
    int M, int N, int K)
{
    __shared__ float sA[2][BMT * SSTR];
    __shared__ float sB[2][BNT * SSTR];

    const int tid = threadIdx.x;
    const int lane = tid & 31;
    const int wid = tid >> 5;
    const int wm = wid >> 2;      // 0..1  (64-row slab)
    const int wn = wid & 3;       // 0..3  (32-col slab)
    const int g = lane >> 2;      // 0..7
    const int t = lane & 3;       // 0..3

    const int bx = blockIdx.x;    // N tile
    const int by = blockIdx.y;    // M tile

    const float* Abase = A + (size_t)(by * BMT) * K;
    const float* Bbase = Bm + (size_t)(bx * BNT) * K;

    const uint32_t sAaddr = smem_u32(&sA[0][0]);
    const uint32_t sBaddr = smem_u32(&sB[0][0]);
    const uint32_t stageBytes = BMT * SSTR * 4;

    float acc[4][4][4];
#pragma unroll
    for (int i = 0; i < 4; i++)
#pragma unroll
        for (int j = 0; j < 4; j++)
#pragma unroll
            for (int e = 0; e < 4; e++) acc[i][j][e] = 0.0f;

    // ---- async load of one stage (A and B 128x16 tiles) ----
    auto load_stage = [&](int st, int kt) {
#pragma unroll
        for (int i = 0; i < 2; i++) {
            int idx = tid + i * 256;
            int row = idx >> 2, c = idx & 3;
            uint32_t off = (uint32_t)(row * SSTR + c * 4) * 4;
            cp16(sAaddr + st * stageBytes + off,
                 Abase + (size_t)row * K + kt + c * 4);
            cp16(sBaddr + st * stageBytes + off,
                 Bbase + (size_t)row * K + kt + c * 4);
        }
    };

    load_stage(0, 0);
    CP_COMMIT();

    const int KITERS = K / BKT;   // 64
    for (int it = 0; it < KITERS; it++) {
        int nxt = it + 1;
        if (nxt < KITERS) load_stage(nxt & 1, nxt * BKT);
        CP_COMMIT();
        CP_WAIT1();
        __syncthreads();

        const float* a_s = sA[it & 1];
        const float* b_s = sB[it & 1];

        // Load + split fragments
        uint32_t Ahi[4][4], Alo[4][4], Bhi[4][2], Blo[4][2];
#pragma unroll
        for (int mf = 0; mf < 4; mf++) {
            int r0 = wm * 64 + mf * 16 + g;
            float2 x0 = *(const float2*)&a_s[r0 * SSTR + 2 * t];
            float2 x1 = *(const float2*)&a_s[(r0 + 8) * SSTR + 2 * t];
            float2 x2 = *(const float2*)&a_s[r0 * SSTR + 2 * t + 8];
            float2 x3 = *(const float2*)&a_s[(r0 + 8) * SSTR + 2 * t + 8];
            split2(x0.x, x0.y, Ahi[mf][0], Alo[mf][0]);
            split2(x1.x, x1.y, Ahi[mf][1], Alo[mf][1]);
            split2(x2.x, x2.y, Ahi[mf][2], Alo[mf][2]);
            split2(x3.x, x3.y, Ahi[mf][3], Alo[mf][3]);
        }
#pragma unroll
        for (int nf = 0; nf < 4; nf++) {
            int n = wn * 32 + nf * 8 + g;
            float2 y0 = *(const float2*)&b_s[n * SSTR + 2 * t];
            float2 y1 = *(const float2*)&b_s[n * SSTR + 2 * t + 8];
            split2(y0.x, y0.y, Bhi[nf][0], Blo[nf][0]);
            split2(y1.x, y1.y, Bhi[nf][1], Blo[nf][1]);
        }

#pragma unroll
        for (int mf = 0; mf < 4; mf++)
#pragma unroll
            for (int nf = 0; nf < 4; nf++) {
                float* c = acc[mf][nf];
                mma_bf16(c, Ahi[mf][0], Ahi[mf][1], Ahi[mf][2], Ahi[mf][3],
                         Bhi[nf][0], Bhi[nf][1]);
                mma_bf16(c, Ahi[mf][0], Ahi[mf][1], Ahi[mf][2], Ahi[mf][3],
                         Blo[nf][0], Blo[nf][1]);
                mma_bf16(c, Alo[mf][0], Alo[mf][1], Alo[mf][2], Alo[mf][3],
                         Bhi[nf][0], Bhi[nf][1]);
            }
        __syncthreads();
    }

    // ---- epilogue: bias + store ----
#pragma unroll
    for (int mf = 0; mf < 4; mf++) {
#pragma unroll
        for (int nf = 0; nf < 4; nf++) {
            int row0 = by * BMT + wm * 64 + mf * 16 + g;
            int col = bx * BNT + wn * 32 + nf * 8 + 2 * t;
            float b0 = bias[col], b1 = bias[col + 1];
            float2 o0, o1;
            o0.x = acc[mf][nf][0] + b0; o0.y = acc[mf][nf][1] + b1;
            o1.x = acc[mf][nf][2] + b0; o1.y = acc[mf][nf][3] + b1;
            *(float2*)(C + (size_t)row0 * N + col) = o0;
            *(float2*)(C + (size_t)(row0 + 8) * N + col) = o1;
        }
    }
}

// ---------------------------------------------------------------------------
// Flash attention, fp32 (unchanged — known good).
// ---------------------------------------------------------------------------
__global__ __launch_bounds__(128) void flash_attn_f32(
    const float* __restrict__ Q, const float* __restrict__ Kt,
    const float* __restrict__ Vt, float* __restrict__ O)
{
    const int bh = blockIdx.y;
    const int b = bh / HEADS, h = bh % HEADS;
    const int q0 = blockIdx.x * 64;
    const int tid = threadIdx.x;
    const int r = tid >> 1;
    const int half = tid & 1;

    __shared__ float Ks[32][64];
    __shared__ float Vs[32][64];

    const size_t bhOff = (size_t)b * SEQ * DIM + (size_t)h * HDIM;
    const float* Qb = Q + bhOff;
    const float* Kb = Kt + bhOff;
    const float* Vb = Vt + bhOff;

    float q[32];
    {
        const float* qp = Qb + (size_t)(q0 + r) * DIM + half * 32;
#pragma unroll
        for (int i = 0; i < 32; i += 4) {
            float4 v = *(const float4*)(qp + i);
            q[i + 0] = v.x * 8.0f; q[i + 1] = v.y * 8.0f;
            q[i + 2] = v.z * 8.0f; q[i + 3] = v.w * 8.0f;
        }
    }

    float m = -INFINITY, l = 0.0f;
    float acc[32];
#pragma unroll
    for (int c = 0; c < 32; c++) acc[c] = 0.0f;

    for (int t0 = 0; t0 < SEQ; t0 += 32) {
        __syncthreads();
#pragma unroll
        for (int f = tid; f < 512; f += 128) {
            int rr = f >> 4;
            int cc = (f & 15) << 2;
            *(float4*)&Ks[rr][cc] =
                *(const float4*)(Kb + (size_t)(t0 + rr) * DIM + cc);
            *(float4*)&Vs[rr][cc] =
                *(const float4*)(Vb + (size_t)(t0 + rr) * DIM + cc);
        }
        __syncthreads();

        float s[32];
#pragma unroll
        for (int j = 0; j < 32; j++) s[j] = 0.0f;
        for (int kk = 0; kk < 32; kk++) {
            float qv = q[kk];
            int kcol = half * 32 + kk;
#pragma unroll
            for (int j = 0; j < 32; j++)
                s[j] += qv * Ks[j][kcol];
        }
#pragma unroll
        for (int j = 0; j < 32; j++)
            s[j] += __shfl_xor_sync(0xffffffffu, s[j], 1);

        float mt = s[0];
#pragma unroll
        for (int j = 1; j < 32; j++) mt = fmaxf(mt, s[j]);
        float mnew = fmaxf(m, mt);
        float corr = __expf(m - mnew);
        float lsum = 0.0f;
#pragma unroll
        for (int j = 0; j < 32; j++) {
            s[j] = __expf(s[j] - mnew);
            lsum += s[j];
        }
        l = l * corr + lsum;
        m = mnew;
#pragma unroll
        for (int c = 0; c < 32; c++) acc[c] *= corr;

        for (int j = 0; j < 32; j++) {
            float p = s[j];
            const float* vrow = &Vs[j][half * 32];
#pragma unroll
            for (int c = 0; c < 32; c += 4) {
                float4 v = *(const float4*)(vrow + c);
                acc[c + 0] += p * v.x; acc[c + 1] += p * v.y;
                acc[c + 2] += p * v.z; acc[c + 3] += p * v.w;
            }
        }
    }

    float inv = 1.0f / l;
    float* op = O + bhOff + (size_t)(q0 + r) * DIM + half * 32;
#pragma unroll
    for (int c = 0; c < 32; c += 4) {
        float4 o;
        o.x = acc[c + 0] * inv; o.y = acc[c + 1] * inv;
        o.z = acc[c + 2] * inv; o.w = acc[c + 3] * inv;
        *(float4*)(op + c) = o;
    }
}

// ---------------------------------------------------------------------------
extern "C" void kernel_launch(void* const* d_in, const int* in_sizes, int n_in,
                              void* d_out, int out_size)
{
    (void)in_sizes; (void)n_in; (void)out_size;
    const float* query = (const float*)d_in[0];
    const float* key   = (const float*)d_in[1];
    const float* value = (const float*)d_in[2];
    const float* Wq = (const float*)d_in[3];
    const float* bq = (const float*)d_in[4];
    const float* Wk = (const float*)d_in[5];
    const float* bk = (const float*)d_in[6];
    const float* Wv = (const float*)d_in[7];
    const float* bv = (const float*)d_in[8];
    const float* Wo = (const float*)d_in[9];
    const float* bo = (const float*)d_in[10];
    float* out = (float*)d_out;

    float *qbuf, *kbuf, *vbuf, *abuf;
    cudaGetSymbolAddress((void**)&qbuf, g_Q);
    cudaGetSymbolAddress((void**)&kbuf, g_K);
    cudaGetSymbolAddress((void**)&vbuf, g_V);
    cudaGetSymbolAddress((void**)&abuf, g_A);

    dim3 gemmGrid(DIM / 128, MROWS / 128);   // (8, 32)
    gemm_mma_bf16x3<<<gemmGrid, 256>>>(query, Wq, bq, qbuf, MROWS, DIM, DIM);
    gemm_mma_bf16x3<<<gemmGrid, 256>>>(key,   Wk, bk, kbuf, MROWS, DIM, DIM);
    gemm_mma_bf16x3<<<gemmGrid, 256>>>(value, Wv, bv, vbuf, MROWS, DIM, DIM);

    dim3 attnGrid(SEQ / 64, BATCH * HEADS);  // (32, 32)
    flash_attn_f32<<<attnGrid, 128>>>(qbuf, kbuf, vbuf, abuf);

    gemm_mma_bf16x3<<<gemmGrid, 256>>>(abuf, Wo, bo, out, MROWS, DIM, DIM);
}

// round 6
// speedup vs baseline: 4.1338x; 3.8244x over previous
#include <cuda_runtime.h>
#include <cuda_bf16.h>
#include <math.h>
#include <stdint.h>

// Problem constants
#define BATCH 2
#define SEQ   2048
#define DIM   1024
#define HEADS 16
#define HDIM  64
#define MROWS (BATCH * SEQ)   // 4096

// Scratch (device globals: allocation-free)
__device__ float g_Q[MROWS * DIM];
__device__ float g_K[MROWS * DIM];
__device__ float g_V[MROWS * DIM];
__device__ float g_A[MROWS * DIM];

// ===========================================================================
// Helpers
// ===========================================================================
__device__ __forceinline__ uint32_t smem_u32(const void* p) {
    uint32_t a;
    asm("{ .reg .u64 t; cvta.to.shared.u64 t, %1; cvt.u32.u64 %0, t; }"
        : "=r"(a) : "l"(p));
    return a;
}

__device__ __forceinline__ void cp16(uint32_t dst, const void* src) {
    asm volatile("cp.async.cg.shared.global [%0], [%1], 16;"
                 :: "r"(dst), "l"(src));
}
#define CP_COMMIT() asm volatile("cp.async.commit_group;" ::: "memory")
#define CP_WAIT1()  asm volatile("cp.async.wait_group 1;" ::: "memory")

__device__ __forceinline__ uint32_t packbf(float a, float b) {
    __nv_bfloat162 r = __halves2bfloat162(__float2bfloat16_rn(a),
                                          __float2bfloat16_rn(b));
    return *reinterpret_cast<uint32_t*>(&r);
}

// Split float pair into bf16 hi / lo packed registers
__device__ __forceinline__ void split2(float x0, float x1,
                                       uint32_t& hi, uint32_t& lo) {
    __nv_bfloat16 h0 = __float2bfloat16_rn(x0);
    __nv_bfloat16 h1 = __float2bfloat16_rn(x1);
    float r0 = x0 - __bfloat162float(h0);
    float r1 = x1 - __bfloat162float(h1);
    __nv_bfloat162 hh = __halves2bfloat162(h0, h1);
    __nv_bfloat162 ll = __halves2bfloat162(__float2bfloat16_rn(r0),
                                           __float2bfloat16_rn(r1));
    hi = *reinterpret_cast<uint32_t*>(&hh);
    lo = *reinterpret_cast<uint32_t*>(&ll);
}

__device__ __forceinline__ void mma_bf16(float* c, uint32_t a0, uint32_t a1,
                                         uint32_t a2, uint32_t a3,
                                         uint32_t b0, uint32_t b1) {
    asm volatile(
        "mma.sync.aligned.m16n8k16.row.col.f32.bf16.bf16.f32 "
        "{%0,%1,%2,%3}, {%4,%5,%6,%7}, {%8,%9}, {%0,%1,%2,%3};"
        : "+f"(c[0]), "+f"(c[1]), "+f"(c[2]), "+f"(c[3])
        : "r"(a0), "r"(a1), "r"(a2), "r"(a3), "r"(b0), "r"(b1));
}

// ===========================================================================
// GEMM: C[M,N] = A[M,K] * B[N,K]^T + bias[N]  (unchanged, known-good)
// ===========================================================================
#define BMT 128
#define BNT 128
#define BKT 16
#define SSTR 20

__global__ __launch_bounds__(256, 1) void gemm_mma_bf16x3(
    const float* __restrict__ A, const float* __restrict__ Bm,
    const float* __restrict__ bias, float* __restrict__ C,
    int M, int N, int K)
{
    __shared__ float sA[2][BMT * SSTR];
    __shared__ float sB[2][BNT * SSTR];

    const int tid = threadIdx.x;
    const int lane = tid & 31;
    const int wid = tid >> 5;
    const int wm = wid >> 2;
    const int wn = wid & 3;
    const int g = lane >> 2;
    const int t = lane & 3;

    const int bx = blockIdx.x;
    const int by = blockIdx.y;

    const float* Abase = A + (size_t)(by * BMT) * K;
    const float* Bbase = Bm + (size_t)(bx * BNT) * K;

    const uint32_t sAaddr = smem_u32(&sA[0][0]);
    const uint32_t sBaddr = smem_u32(&sB[0][0]);
    const uint32_t stageBytes = BMT * SSTR * 4;

    float acc[4][4][4];
#pragma unroll
    for (int i = 0; i < 4; i++)
#pragma unroll
        for (int j = 0; j < 4; j++)
#pragma unroll
            for (int e = 0; e < 4; e++) acc[i][j][e] = 0.0f;

    auto load_stage = [&](int st, int kt) {
#pragma unroll
        for (int i = 0; i < 2; i++) {
            int idx = tid + i * 256;
            int row = idx >> 2, c = idx & 3;
            uint32_t off = (uint32_t)(row * SSTR + c * 4) * 4;
            cp16(sAaddr + st * stageBytes + off,
                 Abase + (size_t)row * K + kt + c * 4);
            cp16(sBaddr + st * stageBytes + off,
                 Bbase + (size_t)row * K + kt + c * 4);
        }
    };

    load_stage(0, 0);
    CP_COMMIT();

    const int KITERS = K / BKT;
    for (int it = 0; it < KITERS; it++) {
        int nxt = it + 1;
        if (nxt < KITERS) load_stage(nxt & 1, nxt * BKT);
        CP_COMMIT();
        CP_WAIT1();
        __syncthreads();

        const float* a_s = sA[it & 1];
        const float* b_s = sB[it & 1];

        uint32_t Ahi[4][4], Alo[4][4], Bhi[4][2], Blo[4][2];
#pragma unroll
        for (int mf = 0; mf < 4; mf++) {
            int r0 = wm * 64 + mf * 16 + g;
            float2 x0 = *(const float2*)&a_s[r0 * SSTR + 2 * t];
            float2 x1 = *(const float2*)&a_s[(r0 + 8) * SSTR + 2 * t];
            float2 x2 = *(const float2*)&a_s[r0 * SSTR + 2 * t + 8];
            float2 x3 = *(const float2*)&a_s[(r0 + 8) * SSTR + 2 * t + 8];
            split2(x0.x, x0.y, Ahi[mf][0], Alo[mf][0]);
            split2(x1.x, x1.y, Ahi[mf][1], Alo[mf][1]);
            split2(x2.x, x2.y, Ahi[mf][2], Alo[mf][2]);
            split2(x3.x, x3.y, Ahi[mf][3], Alo[mf][3]);
        }
#pragma unroll
        for (int nf = 0; nf < 4; nf++) {
            int n = wn * 32 + nf * 8 + g;
            float2 y0 = *(const float2*)&b_s[n * SSTR + 2 * t];
            float2 y1 = *(const float2*)&b_s[n * SSTR + 2 * t + 8];
            split2(y0.x, y0.y, Bhi[nf][0], Blo[nf][0]);
            split2(y1.x, y1.y, Bhi[nf][1], Blo[nf][1]);
        }

#pragma unroll
        for (int mf = 0; mf < 4; mf++)
#pragma unroll
            for (int nf = 0; nf < 4; nf++) {
                float* c = acc[mf][nf];
                mma_bf16(c, Ahi[mf][0], Ahi[mf][1], Ahi[mf][2], Ahi[mf][3],
                         Bhi[nf][0], Bhi[nf][1]);
                mma_bf16(c, Ahi[mf][0], Ahi[mf][1], Ahi[mf][2], Ahi[mf][3],
                         Blo[nf][0], Blo[nf][1]);
                mma_bf16(c, Alo[mf][0], Alo[mf][1], Alo[mf][2], Alo[mf][3],
                         Bhi[nf][0], Bhi[nf][1]);
            }
        __syncthreads();
    }

#pragma unroll
    for (int mf = 0; mf < 4; mf++) {
#pragma unroll
        for (int nf = 0; nf < 4; nf++) {
            int row0 = by * BMT + wm * 64 + mf * 16 + g;
            int col = bx * BNT + wn * 32 + nf * 8 + 2 * t;
            float b0 = bias[col], b1 = bias[col + 1];
            float2 o0, o1;
            o0.x = acc[mf][nf][0] + b0; o0.y = acc[mf][nf][1] + b1;
            o1.x = acc[mf][nf][2] + b0; o1.y = acc[mf][nf][3] + b1;
            *(float2*)(C + (size_t)row0 * N + col) = o0;
            *(float2*)(C + (size_t)(row0 + 8) * N + col) = o1;
        }
    }
}

// ===========================================================================
// Tensor-core flash attention (bf16x3 compensated QK^T and PV).
// Block: 128 q rows x one (b,h). 256 threads = 8 warps; warp w owns rows
// w*16..w*16+15. K-tile = 64 tokens. grid = (SEQ/128, BATCH*HEADS).
// Smem rows padded to 144B (72 halfs) -> B-frag banks 4g+t all distinct.
// ===========================================================================
#define KSTR 72                     // halfs per smem row (144 bytes)
#define ATT_SMEM ((128*KSTR*2 + 64*KSTR*4) * 2)   // Q hi/lo + K,V hi/lo (bytes)

__global__ __launch_bounds__(256, 1) void flash_attn_mma(
    const float* __restrict__ Q, const float* __restrict__ Kg,
    const float* __restrict__ Vg, float* __restrict__ O)
{
    extern __shared__ char smem[];
    __nv_bfloat16* QH = (__nv_bfloat16*)smem;
    __nv_bfloat16* QL = QH + 128 * KSTR;
    __nv_bfloat16* KH = QL + 128 * KSTR;
    __nv_bfloat16* KL = KH + 64 * KSTR;
    __nv_bfloat16* VH = KL + 64 * KSTR;
    __nv_bfloat16* VL = VH + 64 * KSTR;

    const int tid = threadIdx.x;
    const int lane = tid & 31;
    const int w = tid >> 5;
    const int g = lane >> 2;
    const int t = lane & 3;

    const int bh = blockIdx.y;
    const int b = bh >> 4, h = bh & 15;
    const int q0 = blockIdx.x * 128;

    const size_t bhOff = (size_t)b * SEQ * DIM + (size_t)h * HDIM;
    const float* Qb = Q + bhOff;
    const float* Kb = Kg + bhOff;
    const float* Vb = Vg + bhOff;

    // K/V prefetch register tiles + store helpers
    const int ktok = tid >> 2, kdg = tid & 3;            // K: 64 tok x 4 thr
    const int vdb = tid >> 6, vtok = tid & 63;           // V: 4 dim-grp x 64 tok
    float kr[16], vr[16];

    auto loadKV = [&](int kt) {
        const float* ks = Kb + (size_t)(kt + ktok) * DIM + kdg * 16;
        const float* vs = Vb + (size_t)(kt + vtok) * DIM + vdb * 16;
#pragma unroll
        for (int i = 0; i < 4; i++) {
            *(float4*)&kr[4 * i] = *(const float4*)(ks + 4 * i);
            *(float4*)&vr[4 * i] = *(const float4*)(vs + 4 * i);
        }
    };
    auto storeKV = [&]() {
        uint32_t* dh = (uint32_t*)(KH + ktok * KSTR + kdg * 16);
        uint32_t* dl = (uint32_t*)(KL + ktok * KSTR + kdg * 16);
#pragma unroll
        for (int p = 0; p < 8; p++) {
            uint32_t hi, lo;
            split2(kr[2 * p], kr[2 * p + 1], hi, lo);
            dh[p] = hi; dl[p] = lo;
        }
#pragma unroll
        for (int j = 0; j < 16; j++) {     // transposed V store
            float x = vr[j];
            __nv_bfloat16 hv = __float2bfloat16_rn(x);
            VH[(vdb * 16 + j) * KSTR + vtok] = hv;
            VL[(vdb * 16 + j) * KSTR + vtok] =
                __float2bfloat16_rn(x - __bfloat162float(hv));
        }
    };

    // ---- prologue: Q tile (scaled x8, split hi/lo), K/V tile 0 ----
    {
        const int row = tid >> 1, half = tid & 1;
        const float* src = Qb + (size_t)(q0 + row) * DIM + half * 32;
        uint32_t* dh = (uint32_t*)(QH + row * KSTR + half * 32);
        uint32_t* dl = (uint32_t*)(QL + row * KSTR + half * 32);
#pragma unroll
        for (int i = 0; i < 8; i++) {
            float4 v = *(const float4*)(src + 4 * i);
            uint32_t h0, l0, h1, l1;
            split2(v.x * 8.0f, v.y * 8.0f, h0, l0);
            split2(v.z * 8.0f, v.w * 8.0f, h1, l1);
            dh[2 * i] = h0; dh[2 * i + 1] = h1;
            dl[2 * i] = l0; dl[2 * i + 1] = l1;
        }
    }
    loadKV(0);
    storeKV();
    __syncthreads();

    // ---- Q fragments (registers, live whole kernel) ----
    uint32_t qh[4][4], ql[4][4];
#pragma unroll
    for (int kf = 0; kf < 4; kf++) {
        const int r0 = w * 16 + g;
        qh[kf][0] = *(uint32_t*)(QH + r0 * KSTR + kf * 16 + 2 * t);
        qh[kf][1] = *(uint32_t*)(QH + (r0 + 8) * KSTR + kf * 16 + 2 * t);
        qh[kf][2] = *(uint32_t*)(QH + r0 * KSTR + kf * 16 + 8 + 2 * t);
        qh[kf][3] = *(uint32_t*)(QH + (r0 + 8) * KSTR + kf * 16 + 8 + 2 * t);
        ql[kf][0] = *(uint32_t*)(QL + r0 * KSTR + kf * 16 + 2 * t);
        ql[kf][1] = *(uint32_t*)(QL + (r0 + 8) * KSTR + kf * 16 + 2 * t);
        ql[kf][2] = *(uint32_t*)(QL + r0 * KSTR + kf * 16 + 8 + 2 * t);
        ql[kf][3] = *(uint32_t*)(QL + (r0 + 8) * KSTR + kf * 16 + 8 + 2 * t);
    }

    float m0 = -INFINITY, m1 = -INFINITY, l0 = 0.0f, l1 = 0.0f;
    float acc[8][4];
#pragma unroll
    for (int nf = 0; nf < 8; nf++)
#pragma unroll
        for (int e = 0; e < 4; e++) acc[nf][e] = 0.0f;

    const int NTILES = SEQ / 64;   // 32
    for (int it = 0; it < NTILES; it++) {
        if (it + 1 < NTILES) loadKV((it + 1) * 64);

        // ---- scores S[16x64] ----
        float s[8][4];
#pragma unroll
        for (int nf = 0; nf < 8; nf++)
#pragma unroll
            for (int e = 0; e < 4; e++) s[nf][e] = 0.0f;

#pragma unroll
        for (int nf = 0; nf < 8; nf++) {
            const int kr0 = (nf * 8 + g) * KSTR;
#pragma unroll
            for (int kf = 0; kf < 4; kf++) {
                uint32_t bh0 = *(uint32_t*)(KH + kr0 + kf * 16 + 2 * t);
                uint32_t bh1 = *(uint32_t*)(KH + kr0 + kf * 16 + 8 + 2 * t);
                uint32_t bl0 = *(uint32_t*)(KL + kr0 + kf * 16 + 2 * t);
                uint32_t bl1 = *(uint32_t*)(KL + kr0 + kf * 16 + 8 + 2 * t);
                mma_bf16(s[nf], qh[kf][0], qh[kf][1], qh[kf][2], qh[kf][3], bh0, bh1);
                mma_bf16(s[nf], ql[kf][0], ql[kf][1], ql[kf][2], ql[kf][3], bh0, bh1);
                mma_bf16(s[nf], qh[kf][0], qh[kf][1], qh[kf][2], qh[kf][3], bl0, bl1);
            }
        }

        // ---- online softmax (rows g and g+8) ----
        float tm0 = -INFINITY, tm1 = -INFINITY;
#pragma unroll
        for (int nf = 0; nf < 8; nf++) {
            tm0 = fmaxf(tm0, fmaxf(s[nf][0], s[nf][1]));
            tm1 = fmaxf(tm1, fmaxf(s[nf][2], s[nf][3]));
        }
        tm0 = fmaxf(tm0, __shfl_xor_sync(0xffffffffu, tm0, 1));
        tm0 = fmaxf(tm0, __shfl_xor_sync(0xffffffffu, tm0, 2));
        tm1 = fmaxf(tm1, __shfl_xor_sync(0xffffffffu, tm1, 1));
        tm1 = fmaxf(tm1, __shfl_xor_sync(0xffffffffu, tm1, 2));

        float mn0 = fmaxf(m0, tm0), mn1 = fmaxf(m1, tm1);
        float c0 = __expf(m0 - mn0), c1 = __expf(m1 - mn1);
        m0 = mn0; m1 = mn1;

        float ls0 = 0.0f, ls1 = 0.0f;
#pragma unroll
        for (int nf = 0; nf < 8; nf++) {
            s[nf][0] = __expf(s[nf][0] - mn0);
            s[nf][1] = __expf(s[nf][1] - mn0);
            s[nf][2] = __expf(s[nf][2] - mn1);
            s[nf][3] = __expf(s[nf][3] - mn1);
            ls0 += s[nf][0] + s[nf][1];
            ls1 += s[nf][2] + s[nf][3];
        }
        ls0 += __shfl_xor_sync(0xffffffffu, ls0, 1);
        ls0 += __shfl_xor_sync(0xffffffffu, ls0, 2);
        ls1 += __shfl_xor_sync(0xffffffffu, ls1, 1);
        ls1 += __shfl_xor_sync(0xffffffffu, ls1, 2);
        l0 = l0 * c0 + ls0;
        l1 = l1 * c1 + ls1;

#pragma unroll
        for (int nf = 0; nf < 8; nf++) {
            acc[nf][0] *= c0; acc[nf][1] *= c0;
            acc[nf][2] *= c1; acc[nf][3] *= c1;
        }

        // ---- pack P into A-fragments (hi + residual lo), pure registers ----
        uint32_t ph[4][4], pl[4][4];
#pragma unroll
        for (int kf = 0; kf < 4; kf++) {
            const float* p0 = s[2 * kf];
            const float* p1 = s[2 * kf + 1];
            split2(p0[0], p0[1], ph[kf][0], pl[kf][0]);
            split2(p0[2], p0[3], ph[kf][1], pl[kf][1]);
            split2(p1[0], p1[1], ph[kf][2], pl[kf][2]);
            split2(p1[2], p1[3], ph[kf][3], pl[kf][3]);
        }

        // ---- acc += P * V  (V transposed in smem: rows=dims, cols=tokens) ----
#pragma unroll
        for (int nf = 0; nf < 8; nf++) {
            const int vr0 = (nf * 8 + g) * KSTR;
#pragma unroll
            for (int kf = 0; kf < 4; kf++) {
                uint32_t bh0 = *(uint32_t*)(VH + vr0 + kf * 16 + 2 * t);
                uint32_t bh1 = *(uint32_t*)(VH + vr0 + kf * 16 + 8 + 2 * t);
                uint32_t bl0 = *(uint32_t*)(VL + vr0 + kf * 16 + 2 * t);
                uint32_t bl1 = *(uint32_t*)(VL + vr0 + kf * 16 + 8 + 2 * t);
                mma_bf16(acc[nf], ph[kf][0], ph[kf][1], ph[kf][2], ph[kf][3], bh0, bh1);
                mma_bf16(acc[nf], pl[kf][0], pl[kf][1], pl[kf][2], pl[kf][3], bh0, bh1);
                mma_bf16(acc[nf], ph[kf][0], ph[kf][1], ph[kf][2], ph[kf][3], bl0, bl1);
            }
        }

        __syncthreads();
        if (it + 1 < NTILES) {
            storeKV();
            __syncthreads();
        }
    }

    // ---- epilogue ----
    const float inv0 = 1.0f / l0;
    const float inv1 = 1.0f / l1;
    const int row0 = q0 + w * 16 + g;
    float* ob = O + bhOff;
#pragma unroll
    for (int nf = 0; nf < 8; nf++) {
        const int col = nf * 8 + 2 * t;
        float2 o0, o1;
        o0.x = acc[nf][0] * inv0; o0.y = acc[nf][1] * inv0;
        o1.x = acc[nf][2] * inv1; o1.y = acc[nf][3] * inv1;
        *(float2*)(ob + (size_t)row0 * DIM + col) = o0;
        *(float2*)(ob + (size_t)(row0 + 8) * DIM + col) = o1;
    }
}

// ---------------------------------------------------------------------------
extern "C" void kernel_launch(void* const* d_in, const int* in_sizes, int n_in,
                              void* d_out, int out_size)
{
    (void)in_sizes; (void)n_in; (void)out_size;
    const float* query = (const float*)d_in[0];
    const float* key   = (const float*)d_in[1];
    const float* value = (const float*)d_in[2];
    const float* Wq = (const float*)d_in[3];
    const float* bq = (const float*)d_in[4];
    const float* Wk = (const float*)d_in[5];
    const float* bk = (const float*)d_in[6];
    const float* Wv = (const float*)d_in[7];
    const float* bv = (const float*)d_in[8];
    const float* Wo = (const float*)d_in[9];
    const float* bo = (const float*)d_in[10];
    float* out = (float*)d_out;

    float *qbuf, *kbuf, *vbuf, *abuf;
    cudaGetSymbolAddress((void**)&qbuf, g_Q);
    cudaGetSymbolAddress((void**)&kbuf, g_K);
    cudaGetSymbolAddress((void**)&vbuf, g_V);
    cudaGetSymbolAddress((void**)&abuf, g_A);

    static bool attrSet = false;
    if (!attrSet) {
        cudaFuncSetAttribute(flash_attn_mma,
                             cudaFuncAttributeMaxDynamicSharedMemorySize,
                             ATT_SMEM);
        attrSet = true;
    }

    dim3 gemmGrid(DIM / 128, MROWS / 128);   // (8, 32)
    gemm_mma_bf16x3<<<gemmGrid, 256>>>(query, Wq, bq, qbuf, MROWS, DIM, DIM);
    gemm_mma_bf16x3<<<gemmGrid, 256>>>(key,   Wk, bk, kbuf, MROWS, DIM, DIM);
    gemm_mma_bf16x3<<<gemmGrid, 256>>>(value, Wv, bv, vbuf, MROWS, DIM, DIM);

    dim3 attnGrid(SEQ / 128, BATCH * HEADS);  // (16, 32)
    flash_attn_mma<<<attnGrid, 256, ATT_SMEM>>>(qbuf, kbuf, vbuf, abuf);

    gemm_mma_bf16x3<<<gemmGrid, 256>>>(abuf, Wo, bo, out, MROWS, DIM, DIM);
}